// round 3
// baseline (speedup 1.0000x reference)
#include <cuda_runtime.h>
#include <cuda_bf16.h>

#define N_MAX 100000
#define NF 128
#define NH 64
#define NC 16

// Scratch (alloc-free rule: __device__ globals)
__device__ float g_h0[N_MAX * NH];   // x @ W1
__device__ float g_h1[N_MAX * NH];   // segment_sum layer 1 (accumulator)
__device__ float g_h2[N_MAX * NC];   // relu(h1) @ W2

// ---------------------------------------------------------------------------
// GEMM1: h0[n,64] = x[n,128] @ W1[128,64]; also zeroes g_h1 rows (runs before
// scatter1 in-stream, so this is safe).
// Block: 256 threads, tile 64 rows x 64 cols, 4x4 microtile per thread.
// ---------------------------------------------------------------------------
__global__ void __launch_bounds__(256) gemm1_kernel(
    const float* __restrict__ x, const float* __restrict__ W1, int n)
{
    __shared__ float ws[NF * NH];    // 32 KB, [k][c]
    __shared__ float xs[32 * 65];    // transposed chunk [k_local][row], pad 65

    int tid = threadIdx.x;
    // Load full W1 (layout matches global)
    #pragma unroll
    for (int i = tid; i < NF * NH / 4; i += 256)
        ((float4*)ws)[i] = ((const float4*)W1)[i];

    int row0 = blockIdx.x * 64;
    int tx = tid & 15, ty = tid >> 4;
    int r0 = ty * 4, c0 = tx * 4;
    int kq = tid & 7;         // which group of 4 k's this thread loads
    int lrow = tid >> 3;      // 0..31

    float acc[4][4] = {};

    for (int kc = 0; kc < 4; kc++) {   // K chunks of 32
        __syncthreads();
        #pragma unroll
        for (int pass = 0; pass < 2; pass++) {
            int row = lrow + pass * 32;
            int grow = row0 + row;
            float4 v = make_float4(0.f, 0.f, 0.f, 0.f);
            if (grow < n)
                v = *(const float4*)&x[grow * NF + kc * 32 + kq * 4];
            xs[(kq * 4 + 0) * 65 + row] = v.x;
            xs[(kq * 4 + 1) * 65 + row] = v.y;
            xs[(kq * 4 + 2) * 65 + row] = v.z;
            xs[(kq * 4 + 3) * 65 + row] = v.w;
        }
        __syncthreads();
        #pragma unroll
        for (int kk = 0; kk < 32; kk++) {
            float4 b = *(const float4*)&ws[(kc * 32 + kk) * NH + c0];
            float a0 = xs[kk * 65 + r0 + 0];
            float a1 = xs[kk * 65 + r0 + 1];
            float a2 = xs[kk * 65 + r0 + 2];
            float a3 = xs[kk * 65 + r0 + 3];
            acc[0][0] += a0 * b.x; acc[0][1] += a0 * b.y; acc[0][2] += a0 * b.z; acc[0][3] += a0 * b.w;
            acc[1][0] += a1 * b.x; acc[1][1] += a1 * b.y; acc[1][2] += a1 * b.z; acc[1][3] += a1 * b.w;
            acc[2][0] += a2 * b.x; acc[2][1] += a2 * b.y; acc[2][2] += a2 * b.z; acc[2][3] += a2 * b.w;
            acc[3][0] += a3 * b.x; acc[3][1] += a3 * b.y; acc[3][2] += a3 * b.z; acc[3][3] += a3 * b.w;
        }
    }

    #pragma unroll
    for (int i = 0; i < 4; i++) {
        int grow = row0 + r0 + i;
        if (grow < n) {
            *(float4*)&g_h0[grow * NH + c0] =
                make_float4(acc[i][0], acc[i][1], acc[i][2], acc[i][3]);
            *(float4*)&g_h1[grow * NH + c0] = make_float4(0.f, 0.f, 0.f, 0.f);
        }
    }
}

// ---------------------------------------------------------------------------
// Scatter1: g_h1[dst] += g_h0[src] * w  over E edges (64 floats per edge).
// 16 threads per edge, each does 1 LDG.128 + 1 red.global.add.v4.f32.
// Edge metadata staged through shared memory.
// ---------------------------------------------------------------------------
__global__ void __launch_bounds__(256) scatter1_kernel(
    const int* __restrict__ ei, const float* __restrict__ ew, int E)
{
    __shared__ int   ssrc[16];
    __shared__ int   sdst[16];
    __shared__ float sw[16];

    int tid = threadIdx.x;
    int ebase = blockIdx.x * 16;
    if (tid < 16) {
        int e = ebase + tid;
        ssrc[tid] = (e < E) ? ei[e] : -1;
    } else if (tid < 32) {
        int e = ebase + (tid - 16);
        sdst[tid - 16] = (e < E) ? ei[E + e] : 0;
    } else if (tid < 48) {
        int e = ebase + (tid - 32);
        sw[tid - 32] = (e < E) ? ew[e] : 0.f;
    }
    __syncthreads();

    int le = tid >> 4, q = tid & 15;
    int s = ssrc[le];
    if (s < 0) return;
    int d = sdst[le];
    float wt = sw[le];

    float4 v = __ldg((const float4*)&g_h0[s * NH + q * 4]);
    float4 r = make_float4(v.x * wt, v.y * wt, v.z * wt, v.w * wt);
    asm volatile("red.global.add.v4.f32 [%0], {%1,%2,%3,%4};"
                 :: "l"(&g_h1[d * NH + q * 4]),
                    "f"(r.x), "f"(r.y), "f"(r.z), "f"(r.w)
                 : "memory");
}

// ---------------------------------------------------------------------------
// GEMM2: h2[n,16] = relu(h1[n,64]) @ W2[64,16]; also zeroes d_out rows
// (runs before scatter2 in-stream).
// Block: 256 threads = 64 rows x 4 col-groups of 4.
// ---------------------------------------------------------------------------
__global__ void __launch_bounds__(256) gemm2_kernel(
    const float* __restrict__ W2, float* __restrict__ out, int n)
{
    __shared__ float ws[NH * NC];    // 4 KB, [k][c]
    __shared__ float hs[64 * 65];    // [row][k], pad 65

    int tid = threadIdx.x;
    #pragma unroll
    for (int i = tid; i < NH * NC / 4; i += 256)
        ((float4*)ws)[i] = ((const float4*)W2)[i];

    int row0 = blockIdx.x * 64;
    #pragma unroll
    for (int idx = tid; idx < 64 * 64; idx += 256) {
        int r = idx >> 6, k = idx & 63;
        int grow = row0 + r;
        float v = 0.f;
        if (grow < n) v = g_h1[grow * NH + k];
        hs[r * 65 + k] = fmaxf(v, 0.f);   // fused ReLU
    }
    __syncthreads();

    int cg = tid & 3, r = tid >> 2;
    float a0 = 0.f, a1 = 0.f, a2 = 0.f, a3 = 0.f;
    #pragma unroll
    for (int k = 0; k < NH; k++) {
        float a = hs[r * 65 + k];
        float4 b = *(const float4*)&ws[k * NC + cg * 4];
        a0 += a * b.x; a1 += a * b.y; a2 += a * b.z; a3 += a * b.w;
    }

    int grow = row0 + r;
    if (grow < n) {
        *(float4*)&g_h2[grow * NC + cg * 4] = make_float4(a0, a1, a2, a3);
        *(float4*)&out[grow * NC + cg * 4]  = make_float4(0.f, 0.f, 0.f, 0.f);
    }
}

// ---------------------------------------------------------------------------
// Scatter2: out[dst] += g_h2[src] * w  (16 floats per edge).
// 4 threads per edge, 64 edges per 256-thread block.
// ---------------------------------------------------------------------------
__global__ void __launch_bounds__(256) scatter2_kernel(
    const int* __restrict__ ei, const float* __restrict__ ew,
    float* __restrict__ out, int E)
{
    __shared__ int   ssrc[64];
    __shared__ int   sdst[64];
    __shared__ float sw[64];

    int tid = threadIdx.x;
    int ebase = blockIdx.x * 64;
    if (tid < 64) {
        int e = ebase + tid;
        ssrc[tid] = (e < E) ? ei[e] : -1;
    } else if (tid < 128) {
        int e = ebase + (tid - 64);
        sdst[tid - 64] = (e < E) ? ei[E + e] : 0;
    } else if (tid < 192) {
        int e = ebase + (tid - 128);
        sw[tid - 128] = (e < E) ? ew[e] : 0.f;
    }
    __syncthreads();

    int le = tid >> 2, q = tid & 3;
    int s = ssrc[le];
    if (s < 0) return;
    int d = sdst[le];
    float wt = sw[le];

    float4 v = __ldg((const float4*)&g_h2[s * NC + q * 4]);
    float4 r = make_float4(v.x * wt, v.y * wt, v.z * wt, v.w * wt);
    asm volatile("red.global.add.v4.f32 [%0], {%1,%2,%3,%4};"
                 :: "l"(&out[d * NC + q * 4]),
                    "f"(r.x), "f"(r.y), "f"(r.z), "f"(r.w)
                 : "memory");
}

// ---------------------------------------------------------------------------
extern "C" void kernel_launch(void* const* d_in, const int* in_sizes, int n_in,
                              void* d_out, int out_size)
{
    const float* x   = (const float*)d_in[0];
    const int*   ei1 = (const int*)  d_in[1];
    const int*   ei2 = (const int*)  d_in[2];
    const float* ew1 = (const float*)d_in[3];
    const float* ew2 = (const float*)d_in[4];
    const float* W1  = (const float*)d_in[5];
    const float* W2  = (const float*)d_in[6];
    float* out = (float*)d_out;

    int n  = in_sizes[0] / NF;
    int E1 = in_sizes[3];
    int E2 = in_sizes[4];
    int nb = (n + 63) / 64;

    gemm1_kernel<<<nb, 256>>>(x, W1, n);
    scatter1_kernel<<<(E1 + 15) / 16, 256>>>(ei1, ew1, E1);
    gemm2_kernel<<<nb, 256>>>(W2, out, n);
    scatter2_kernel<<<(E2 + 63) / 64, 256>>>(ei2, ew2, out, E2);
}

// round 4
// speedup vs baseline: 1.3640x; 1.3640x over previous
#include <cuda_runtime.h>
#include <cuda_bf16.h>

#define N_MAX 100000
#define NF 128
#define NH 64
#define NC 16

// Scratch (alloc-free rule: __device__ globals)
__device__ float g_h0[N_MAX * NH];   // x @ W1
__device__ float g_h1[N_MAX * NH];   // segment_sum layer 1 (accumulator)
__device__ float g_h2[N_MAX * NC];   // relu(h1) @ W2

// ---------------------------------------------------------------------------
// GEMM1: h0[n,64] = x[n,128] @ W1[128,64]; also zeroes g_h1 rows (runs before
// scatter1 in-stream, so this is safe).
// ---------------------------------------------------------------------------
__global__ void __launch_bounds__(256) gemm1_kernel(
    const float* __restrict__ x, const float* __restrict__ W1, int n)
{
    __shared__ float ws[NF * NH];    // 32 KB, [k][c]
    __shared__ float xs[32 * 65];    // transposed chunk [k_local][row], pad 65

    int tid = threadIdx.x;
    #pragma unroll
    for (int i = tid; i < NF * NH / 4; i += 256)
        ((float4*)ws)[i] = ((const float4*)W1)[i];

    int row0 = blockIdx.x * 64;
    int tx = tid & 15, ty = tid >> 4;
    int r0 = ty * 4, c0 = tx * 4;
    int kq = tid & 7;
    int lrow = tid >> 3;

    float acc[4][4] = {};

    for (int kc = 0; kc < 4; kc++) {
        __syncthreads();
        #pragma unroll
        for (int pass = 0; pass < 2; pass++) {
            int row = lrow + pass * 32;
            int grow = row0 + row;
            float4 v = make_float4(0.f, 0.f, 0.f, 0.f);
            if (grow < n)
                v = *(const float4*)&x[grow * NF + kc * 32 + kq * 4];
            xs[(kq * 4 + 0) * 65 + row] = v.x;
            xs[(kq * 4 + 1) * 65 + row] = v.y;
            xs[(kq * 4 + 2) * 65 + row] = v.z;
            xs[(kq * 4 + 3) * 65 + row] = v.w;
        }
        __syncthreads();
        #pragma unroll
        for (int kk = 0; kk < 32; kk++) {
            float4 b = *(const float4*)&ws[(kc * 32 + kk) * NH + c0];
            float a0 = xs[kk * 65 + r0 + 0];
            float a1 = xs[kk * 65 + r0 + 1];
            float a2 = xs[kk * 65 + r0 + 2];
            float a3 = xs[kk * 65 + r0 + 3];
            acc[0][0] += a0 * b.x; acc[0][1] += a0 * b.y; acc[0][2] += a0 * b.z; acc[0][3] += a0 * b.w;
            acc[1][0] += a1 * b.x; acc[1][1] += a1 * b.y; acc[1][2] += a1 * b.z; acc[1][3] += a1 * b.w;
            acc[2][0] += a2 * b.x; acc[2][1] += a2 * b.y; acc[2][2] += a2 * b.z; acc[2][3] += a2 * b.w;
            acc[3][0] += a3 * b.x; acc[3][1] += a3 * b.y; acc[3][2] += a3 * b.z; acc[3][3] += a3 * b.w;
        }
    }

    #pragma unroll
    for (int i = 0; i < 4; i++) {
        int grow = row0 + r0 + i;
        if (grow < n) {
            *(float4*)&g_h0[grow * NH + c0] =
                make_float4(acc[i][0], acc[i][1], acc[i][2], acc[i][3]);
            *(float4*)&g_h1[grow * NH + c0] = make_float4(0.f, 0.f, 0.f, 0.f);
        }
    }
}

// ---------------------------------------------------------------------------
// Scatter1: g_h1[dst] += g_h0[src] * w.  64 edges per 256-thread block,
// 16 lanes per edge, 4 edges per thread. All 4 gather LDG.128s are issued
// back-to-back (MLP=4) before the 4 REDs.
// ---------------------------------------------------------------------------
__global__ void __launch_bounds__(256) scatter1_kernel(
    const int* __restrict__ ei, const float* __restrict__ ew, int E)
{
    __shared__ int   ssrc[64];
    __shared__ int   sdst[64];
    __shared__ float sw[64];

    int tid = threadIdx.x;
    int ebase = blockIdx.x * 64;
    if (tid < 64) {
        int e = ebase + tid;
        ssrc[tid] = (e < E) ? __ldg(&ei[e]) : -1;
    } else if (tid < 128) {
        int e = ebase + (tid - 64);
        sdst[tid - 64] = (e < E) ? __ldg(&ei[E + e]) : 0;
    } else if (tid < 192) {
        int e = ebase + (tid - 128);
        sw[tid - 128] = (e < E) ? __ldg(&ew[e]) : 0.f;
    }
    __syncthreads();

    int g = tid >> 4;          // edge-slot 0..15
    int q = tid & 15;          // feature quad 0..15

    int   s[4], d[4];
    float w[4];
    float4 v[4];

    #pragma unroll
    for (int u = 0; u < 4; u++) {
        int le = g + u * 16;
        s[u] = ssrc[le];
        d[u] = sdst[le];
        w[u] = sw[le];
    }
    // Batch the gathers — 4 outstanding LDG.128s
    #pragma unroll
    for (int u = 0; u < 4; u++) {
        v[u] = make_float4(0.f, 0.f, 0.f, 0.f);
        if (s[u] >= 0)
            v[u] = __ldg((const float4*)&g_h0[s[u] * NH + q * 4]);
    }
    #pragma unroll
    for (int u = 0; u < 4; u++) {
        if (s[u] >= 0) {
            float wt = w[u];
            asm volatile("red.global.add.v4.f32 [%0], {%1,%2,%3,%4};"
                         :: "l"(&g_h1[d[u] * NH + q * 4]),
                            "f"(v[u].x * wt), "f"(v[u].y * wt),
                            "f"(v[u].z * wt), "f"(v[u].w * wt)
                         : "memory");
        }
    }
}

// ---------------------------------------------------------------------------
// GEMM2: h2[n,16] = relu(h1[n,64]) @ W2[64,16]; also zeroes d_out rows.
// ---------------------------------------------------------------------------
__global__ void __launch_bounds__(256) gemm2_kernel(
    const float* __restrict__ W2, float* __restrict__ out, int n)
{
    __shared__ float ws[NH * NC];
    __shared__ float hs[64 * 65];

    int tid = threadIdx.x;
    #pragma unroll
    for (int i = tid; i < NH * NC / 4; i += 256)
        ((float4*)ws)[i] = ((const float4*)W2)[i];

    int row0 = blockIdx.x * 64;
    #pragma unroll
    for (int idx = tid; idx < 64 * 64; idx += 256) {
        int r = idx >> 6, k = idx & 63;
        int grow = row0 + r;
        float v = 0.f;
        if (grow < n) v = g_h1[grow * NH + k];
        hs[r * 65 + k] = fmaxf(v, 0.f);
    }
    __syncthreads();

    int cg = tid & 3, r = tid >> 2;
    float a0 = 0.f, a1 = 0.f, a2 = 0.f, a3 = 0.f;
    #pragma unroll
    for (int k = 0; k < NH; k++) {
        float a = hs[r * 65 + k];
        float4 b = *(const float4*)&ws[k * NC + cg * 4];
        a0 += a * b.x; a1 += a * b.y; a2 += a * b.z; a3 += a * b.w;
    }

    int grow = row0 + r;
    if (grow < n) {
        *(float4*)&g_h2[grow * NC + cg * 4] = make_float4(a0, a1, a2, a3);
        *(float4*)&out[grow * NC + cg * 4]  = make_float4(0.f, 0.f, 0.f, 0.f);
    }
}

// ---------------------------------------------------------------------------
// Scatter2: out[dst] += g_h2[src] * w.  256 edges per 256-thread block,
// 4 lanes per edge, 4 edges per thread (MLP=4).
// ---------------------------------------------------------------------------
__global__ void __launch_bounds__(256) scatter2_kernel(
    const int* __restrict__ ei, const float* __restrict__ ew,
    float* __restrict__ out, int E)
{
    __shared__ int   ssrc[256];
    __shared__ int   sdst[256];
    __shared__ float sw[256];

    int tid = threadIdx.x;
    int ebase = blockIdx.x * 256;
    {
        int e = ebase + tid;
        ssrc[tid] = (e < E) ? __ldg(&ei[e]) : -1;
        sdst[tid] = (e < E) ? __ldg(&ei[E + e]) : 0;
        sw[tid]   = (e < E) ? __ldg(&ew[e]) : 0.f;
    }
    __syncthreads();

    int g = tid >> 2;          // edge-slot 0..63
    int q = tid & 3;           // feature quad 0..3

    int   s[4], d[4];
    float w[4];
    float4 v[4];

    #pragma unroll
    for (int u = 0; u < 4; u++) {
        int le = g + u * 64;
        s[u] = ssrc[le];
        d[u] = sdst[le];
        w[u] = sw[le];
    }
    #pragma unroll
    for (int u = 0; u < 4; u++) {
        v[u] = make_float4(0.f, 0.f, 0.f, 0.f);
        if (s[u] >= 0)
            v[u] = __ldg((const float4*)&g_h2[s[u] * NC + q * 4]);
    }
    #pragma unroll
    for (int u = 0; u < 4; u++) {
        if (s[u] >= 0) {
            float wt = w[u];
            asm volatile("red.global.add.v4.f32 [%0], {%1,%2,%3,%4};"
                         :: "l"(&out[d[u] * NC + q * 4]),
                            "f"(v[u].x * wt), "f"(v[u].y * wt),
                            "f"(v[u].z * wt), "f"(v[u].w * wt)
                         : "memory");
        }
    }
}

// ---------------------------------------------------------------------------
extern "C" void kernel_launch(void* const* d_in, const int* in_sizes, int n_in,
                              void* d_out, int out_size)
{
    const float* x   = (const float*)d_in[0];
    const int*   ei1 = (const int*)  d_in[1];
    const int*   ei2 = (const int*)  d_in[2];
    const float* ew1 = (const float*)d_in[3];
    const float* ew2 = (const float*)d_in[4];
    const float* W1  = (const float*)d_in[5];
    const float* W2  = (const float*)d_in[6];
    float* out = (float*)d_out;

    int n  = in_sizes[0] / NF;
    int E1 = in_sizes[3];
    int E2 = in_sizes[4];
    int nb = (n + 63) / 64;

    gemm1_kernel<<<nb, 256>>>(x, W1, n);
    scatter1_kernel<<<(E1 + 63) / 64, 256>>>(ei1, ew1, E1);
    gemm2_kernel<<<nb, 256>>>(W2, out, n);
    scatter2_kernel<<<(E2 + 255) / 256, 256>>>(ei2, ew2, out, E2);
}